// round 3
// baseline (speedup 1.0000x reference)
#include <cuda_runtime.h>
#include <cstddef>
#include <cstdint>

// Shapes (fixed by the problem):
// B=32, T=32, K=196, H=512, A=512
#define Bv   32
#define Tv   32
#define Kv   196
#define Hv   512
#define Av   512

// ---------------- scratch (no cudaMalloc allowed) ----------------
__device__ float g_cv[Bv * Kv * Av];   // att_feats @ Wv   (6272 x 512) ~12.85MB
__device__ float g_cg[Bv * Tv * Av];   // hiddens   @ Wg   (1024 x 512)
__device__ float g_cs[Bv * Tv * Av];   // sentinel  @ Ws   (1024 x 512)
__device__ float g_z [Bv * Tv * Kv];   // z_t logits       (1024 x 196)

// ---------------- helpers ----------------
__device__ __forceinline__ float fast_tanh(float x) {
    float y;
    asm("tanh.approx.f32 %0, %1;" : "=f"(y) : "f"(x));
    return y;
}

__device__ __forceinline__ float warp_sum(float v) {
#pragma unroll
    for (int o = 16; o > 0; o >>= 1) v += __shfl_xor_sync(0xffffffffu, v, o);
    return v;
}

__device__ __forceinline__ float warp_max(float v) {
#pragma unroll
    for (int o = 16; o > 0; o >>= 1) v = fmaxf(v, __shfl_xor_sync(0xffffffffu, v, o));
    return v;
}

// ---------------- SGEMM: C[MxN] = A[MxK] * W[KxN], all row-major ----------------
// BM=128, BN=64, BK=16, 256 threads, each thread 8x4. M%128==0, N%64==0, K%16==0.
__global__ __launch_bounds__(256) void sgemm_128x64(
    const float* __restrict__ A, const float* __restrict__ W,
    float* __restrict__ C, int M, int N, int K)
{
    constexpr int BM = 128, BN = 64, BK = 16;
    __shared__ float As[BK][BM];
    __shared__ float Bs[BK][BN];

    const int tid = threadIdx.x;
    const int tx = tid & 15;        // 0..15 -> N
    const int ty = tid >> 4;        // 0..15 -> M
    const int row0 = blockIdx.y * BM;
    const int col0 = blockIdx.x * BN;

    const int aRow = tid >> 2;          // 0..63
    const int aCol = (tid & 3) * 4;     // 0,4,8,12
    const int bRow = tid >> 4;          // 0..15
    const int bCol = (tid & 15) * 4;    // 0..60

    float acc[8][4];
#pragma unroll
    for (int i = 0; i < 8; i++)
#pragma unroll
        for (int j = 0; j < 4; j++) acc[i][j] = 0.f;

    for (int kk = 0; kk < K; kk += BK) {
        float4 a0 = *(const float4*)&A[(size_t)(row0 + aRow) * K + kk + aCol];
        float4 a1 = *(const float4*)&A[(size_t)(row0 + aRow + 64) * K + kk + aCol];
        float4 bv = *(const float4*)&W[(size_t)(kk + bRow) * N + col0 + bCol];

        As[aCol + 0][aRow] = a0.x; As[aCol + 1][aRow] = a0.y;
        As[aCol + 2][aRow] = a0.z; As[aCol + 3][aRow] = a0.w;
        As[aCol + 0][aRow + 64] = a1.x; As[aCol + 1][aRow + 64] = a1.y;
        As[aCol + 2][aRow + 64] = a1.z; As[aCol + 3][aRow + 64] = a1.w;
        *(float4*)&Bs[bRow][bCol] = bv;
        __syncthreads();

#pragma unroll
        for (int k = 0; k < BK; k++) {
            float4 av0 = *(const float4*)&As[k][ty * 8];
            float4 av1 = *(const float4*)&As[k][ty * 8 + 4];
            float4 bvv = *(const float4*)&Bs[k][tx * 4];
            float av[8] = {av0.x, av0.y, av0.z, av0.w, av1.x, av1.y, av1.z, av1.w};
            float bb[4] = {bvv.x, bvv.y, bvv.z, bvv.w};
#pragma unroll
            for (int i = 0; i < 8; i++)
#pragma unroll
                for (int j = 0; j < 4; j++)
                    acc[i][j] = fmaf(av[i], bb[j], acc[i][j]);
        }
        __syncthreads();
    }

#pragma unroll
    for (int i = 0; i < 8; i++) {
        int r = row0 + ty * 8 + i;
        float4 v = make_float4(acc[i][0], acc[i][1], acc[i][2], acc[i][3]);
        *(float4*)&C[(size_t)r * N + col0 + tx * 4] = v;
    }
}

// ---------------- z_t kernel ----------------
// z[b,t,k] = sum_a tanh(cv[b,k,a] + cg[b,t,a]) * wh[a]
// grid (14 k-tiles, 32 b), 256 threads. cv row in registers (read once),
// cg cached in shared in two 16-row passes (32KB static smem).
__global__ __launch_bounds__(256) void zt_kernel(
    const float* __restrict__ cv, const float* __restrict__ cg,
    const float* __restrict__ wh, float* __restrict__ z)
{
    __shared__ float cg_sh[16 * Av];
    const int b = blockIdx.y;
    const int ktile = blockIdx.x;      // 0..13, 14 k's each
    const int tid = threadIdx.x;
    const int w = tid >> 5, lane = tid & 31;

    float whr[16];
#pragma unroll
    for (int i = 0; i < 16; i++) whr[i] = __ldg(wh + i * 32 + lane);

    for (int th = 0; th < 2; th++) {
        __syncthreads();
        const float4* src = (const float4*)(cg + ((size_t)b * Tv + th * 16) * Av);
        float4* dst = (float4*)cg_sh;
        for (int i = tid; i < 16 * Av / 4; i += 256) dst[i] = src[i];
        __syncthreads();

        for (int kl = w; kl < 14; kl += 8) {
            const int k = ktile * 14 + kl;
            const float* cvrow = cv + ((size_t)b * Kv + k) * Av + lane;
            float cvr[16];
#pragma unroll
            for (int i = 0; i < 16; i++) cvr[i] = cvrow[i * 32];

#pragma unroll 2
            for (int t = 0; t < 16; t++) {
                const float* cgrow = cg_sh + t * Av + lane;
                float s = 0.f;
#pragma unroll
                for (int i = 0; i < 16; i++)
                    s = fmaf(fast_tanh(cvr[i] + cgrow[i * 32]), whr[i], s);
                s = warp_sum(s);
                if (lane == 0)
                    z[((size_t)b * Tv + th * 16 + t) * Kv + k] = s;
            }
        }
    }
}

// ---------------- softmax + sentinel gate ----------------
// One block per (b,t) row. Computes z_ext = sum_a tanh(cs+cg)*wh, then
// alpha = softmax(z_t) over K=196, and beta from softmax([z_t, z_ext]).
__global__ __launch_bounds__(256) void softmax_kernel(
    const float* __restrict__ z, const float* __restrict__ csraw,
    const float* __restrict__ cg, const float* __restrict__ wh,
    float* __restrict__ alpha_out, float* __restrict__ beta_out)
{
    const int row = blockIdx.x;       // b*T + t
    const int tid = threadIdx.x;
    const int w = tid >> 5, lane = tid & 31;
    __shared__ float sred[8];
    __shared__ float sred2[8];

    // z_ext partial
    const float* cs_r = csraw + (size_t)row * Av;
    const float* cg_r = cg + (size_t)row * Av;
    float p = 0.f;
#pragma unroll
    for (int it = 0; it < 2; it++) {
        int a = tid + it * 256;
        p = fmaf(fast_tanh(cs_r[a] + cg_r[a]), __ldg(wh + a), p);
    }
    p = warp_sum(p);
    if (lane == 0) sred[w] = p;

    float v = (tid < Kv) ? z[(size_t)row * Kv + tid] : -1e30f;
    float m = warp_max(v);
    if (lane == 0) sred2[w] = m;
    __syncthreads();

    float zext = 0.f, m1 = -1e30f;
#pragma unroll
    for (int i = 0; i < 8; i++) { zext += sred[i]; m1 = fmaxf(m1, sred2[i]); }
    __syncthreads();

    float e = (tid < Kv) ? __expf(v - m1) : 0.f;
    float s = warp_sum(e);
    if (lane == 0) sred[w] = s;
    __syncthreads();

    float s1 = 0.f;
#pragma unroll
    for (int i = 0; i < 8; i++) s1 += sred[i];

    if (tid < Kv) alpha_out[(size_t)row * Kv + tid] = e / s1;

    if (tid == 0) {
        float m2 = fmaxf(m1, zext);
        float s2 = s1 * __expf(m1 - m2) + __expf(zext - m2);
        beta_out[row] = __expf(zext - m2) / s2;
    }
}

// ---------------- c_t + blend ----------------
// c_t[b,t,h] = sum_k alpha[b,t,k]*att[b,k,h];  chat = beta*sent + (1-beta)*c_t
// grid (H/128, B), 128 threads. alpha row-block cached in shared (25KB).
__global__ __launch_bounds__(128) void ct_kernel(
    const float* __restrict__ att, const float* __restrict__ alpha,
    const float* __restrict__ beta, const float* __restrict__ sent,
    float* __restrict__ chat)
{
    __shared__ float al[Tv * Kv];
    __shared__ float be[Tv];
    const int b = blockIdx.y;
    const int h0 = blockIdx.x * 128;
    const int tid = threadIdx.x;

    for (int i = tid; i < Tv * Kv; i += 128) al[i] = alpha[(size_t)b * Tv * Kv + i];
    if (tid < Tv) be[tid] = beta[b * Tv + tid];
    __syncthreads();

    const int h = h0 + tid;
    float acc[Tv];
#pragma unroll
    for (int t = 0; t < Tv; t++) acc[t] = 0.f;

    const float* attb = att + (size_t)b * Kv * Hv + h;
#pragma unroll 2
    for (int k = 0; k < Kv; k++) {
        float a = attb[(size_t)k * Hv];
#pragma unroll
        for (int t = 0; t < Tv; t++) acc[t] = fmaf(al[t * Kv + k], a, acc[t]);
    }

#pragma unroll
    for (int t = 0; t < Tv; t++) {
        float bt = be[t];
        size_t idx = ((size_t)b * Tv + t) * Hv + h;
        chat[idx] = bt * sent[idx] + (1.f - bt) * acc[t];
    }
}

// ---------------- launch ----------------
extern "C" void kernel_launch(void* const* d_in, const int* in_sizes, int n_in,
                              void* d_out, int out_size)
{
    const float* att = (const float*)d_in[0];   // (B,K,H)
    const float* hid = (const float*)d_in[1];   // (B,T,H)
    const float* sen = (const float*)d_in[2];   // (B,T,H)
    const float* Wv  = (const float*)d_in[3];   // (H,A)
    const float* Wg  = (const float*)d_in[4];
    const float* Ws  = (const float*)d_in[5];
    const float* wh  = (const float*)d_in[6];   // (A,)

    float* out   = (float*)d_out;
    float* chat  = out;                                  // B*T*H
    float* alpha = out + (size_t)Bv * Tv * Hv;           // B*T*K
    float* beta  = alpha + (size_t)Bv * Tv * Kv;         // B*T

    float *cv, *cg, *cs, *zb;
    cudaGetSymbolAddress((void**)&cv, g_cv);
    cudaGetSymbolAddress((void**)&cg, g_cg);
    cudaGetSymbolAddress((void**)&cs, g_cs);
    cudaGetSymbolAddress((void**)&zb, g_z);

    dim3 gv(Av / 64, (Bv * Kv) / 128);   // 8 x 49
    sgemm_128x64<<<gv, 256>>>(att, Wv, cv, Bv * Kv, Av, Hv);

    dim3 gg(Av / 64, (Bv * Tv) / 128);   // 8 x 8
    sgemm_128x64<<<gg, 256>>>(hid, Wg, cg, Bv * Tv, Av, Hv);
    sgemm_128x64<<<gg, 256>>>(sen, Ws, cs, Bv * Tv, Av, Hv);

    dim3 gz(14, Bv);
    zt_kernel<<<gz, 256>>>(cv, cg, wh, zb);

    softmax_kernel<<<Bv * Tv, 256>>>(zb, cs, cg, wh, alpha, beta);

    dim3 gc(Hv / 128, Bv);
    ct_kernel<<<gc, 128>>>(att, alpha, beta, sen, chat);
}

// round 4
// speedup vs baseline: 1.7773x; 1.7773x over previous
#include <cuda_runtime.h>
#include <cstddef>
#include <cstdint>

// Shapes (fixed by the problem):
// B=32, T=32, K=196, H=512, A=512
#define Bv   32
#define Tv   32
#define Kv   196
#define Hv   512
#define Av   512

// ---------------- scratch (no cudaMalloc allowed) ----------------
__device__ float g_cv[Bv * Kv * Av];   // att_feats @ Wv   (6272 x 512)
__device__ float g_cg[Bv * Tv * Av];   // hiddens   @ Wg   (1024 x 512)
__device__ float g_cs[Bv * Tv * Av];   // sentinel  @ Ws   (1024 x 512)
__device__ float g_z [Bv * Tv * Kv];   // z_t logits       (1024 x 196)

// ---------------- helpers ----------------
__device__ __forceinline__ float fast_tanh(float x) {
    float y;
    asm("tanh.approx.f32 %0, %1;" : "=f"(y) : "f"(x));
    return y;
}

__device__ __forceinline__ uint32_t f2tf32(float x) {
    uint32_t y;
    asm("cvt.rna.tf32.f32 %0, %1;" : "=r"(y) : "f"(x));
    return y;
}

__device__ __forceinline__ void mma_tf32(float c[4], const uint32_t a[4], const uint32_t b[2]) {
    asm volatile(
        "mma.sync.aligned.m16n8k8.row.col.f32.tf32.tf32.f32 "
        "{%0,%1,%2,%3}, {%4,%5,%6,%7}, {%8,%9}, {%0,%1,%2,%3};\n"
        : "+f"(c[0]), "+f"(c[1]), "+f"(c[2]), "+f"(c[3])
        : "r"(a[0]), "r"(a[1]), "r"(a[2]), "r"(a[3]), "r"(b[0]), "r"(b[1]));
}

__device__ __forceinline__ float warp_sum(float v) {
#pragma unroll
    for (int o = 16; o > 0; o >>= 1) v += __shfl_xor_sync(0xffffffffu, v, o);
    return v;
}

__device__ __forceinline__ float warp_max(float v) {
#pragma unroll
    for (int o = 16; o > 0; o >>= 1) v = fmaxf(v, __shfl_xor_sync(0xffffffffu, v, o));
    return v;
}

// ---------------- TF32 tensor-core GEMM ----------------
// C[MxN] = A[MxK] * W[KxN], all row-major fp32 in / fp32 out.
// Tiles: BM=128, BN=64, BK=32. 256 threads = 8 warps in a 4(M) x 2(N) grid,
// each warp computes a 32x32 tile as 2x4 m16n8k8 TF32 mma tiles.
// Requires M%128==0, N%64==0, K%32==0.
__global__ __launch_bounds__(256) void gemm_tf32(
    const float* __restrict__ A, const float* __restrict__ W,
    float* __restrict__ C, int M, int N, int K)
{
    constexpr int BM = 128, BN = 64, BK = 32;
    constexpr int APAD = 4;  // row stride 36 -> bank = 4r+k, conflict-free frag reads
    constexpr int BPAD = 8;  // row stride 72 -> bank = 8k+n, conflict-free frag reads
    __shared__ uint32_t As[BM][BK + APAD];
    __shared__ uint32_t Bs[BK][BN + BPAD];

    const int tid  = threadIdx.x;
    const int wid  = tid >> 5;
    const int lane = tid & 31;
    const int wm   = wid & 3;       // warp M index (0..3)
    const int wn   = wid >> 2;      // warp N index (0..1)
    const int g    = lane >> 2;     // group id 0..7
    const int q    = lane & 3;      // quad lane 0..3

    const int row0 = blockIdx.y * BM;
    const int col0 = blockIdx.x * BN;

    // global-load mapping
    const int aRow[4] = { (tid + 0)   / 8, (tid + 256) / 8, (tid + 512) / 8, (tid + 768) / 8 };
    const int aC4     = (tid & 7) * 4;                         // same for all 4 (tid%8 pattern repeats each 256? no: (tid+i*256)%8 == tid%8) ✓
    const int bRow[2] = { tid / 16, (tid + 256) / 16 };
    const int bC4     = (tid & 15) * 4;

    float4 aPre[4];
    float4 bPre[2];

    // prologue: load tile 0
#pragma unroll
    for (int i = 0; i < 4; i++)
        aPre[i] = *(const float4*)&A[(size_t)(row0 + aRow[i]) * K + aC4];
#pragma unroll
    for (int i = 0; i < 2; i++)
        bPre[i] = *(const float4*)&W[(size_t)bRow[i] * N + col0 + bC4];

    float acc[2][4][4];
#pragma unroll
    for (int mi = 0; mi < 2; mi++)
#pragma unroll
        for (int ni = 0; ni < 4; ni++)
#pragma unroll
            for (int j = 0; j < 4; j++) acc[mi][ni][j] = 0.f;

    for (int kk = 0; kk < K; kk += BK) {
        // store prefetched tile to smem (with tf32 rounding)
#pragma unroll
        for (int i = 0; i < 4; i++) {
            As[aRow[i]][aC4 + 0] = f2tf32(aPre[i].x);
            As[aRow[i]][aC4 + 1] = f2tf32(aPre[i].y);
            As[aRow[i]][aC4 + 2] = f2tf32(aPre[i].z);
            As[aRow[i]][aC4 + 3] = f2tf32(aPre[i].w);
        }
#pragma unroll
        for (int i = 0; i < 2; i++) {
            Bs[bRow[i]][bC4 + 0] = f2tf32(bPre[i].x);
            Bs[bRow[i]][bC4 + 1] = f2tf32(bPre[i].y);
            Bs[bRow[i]][bC4 + 2] = f2tf32(bPre[i].z);
            Bs[bRow[i]][bC4 + 3] = f2tf32(bPre[i].w);
        }
        __syncthreads();

        // prefetch next tile (overlaps with mma compute below)
        if (kk + BK < K) {
#pragma unroll
            for (int i = 0; i < 4; i++)
                aPre[i] = *(const float4*)&A[(size_t)(row0 + aRow[i]) * K + kk + BK + aC4];
#pragma unroll
            for (int i = 0; i < 2; i++)
                bPre[i] = *(const float4*)&W[(size_t)(kk + BK + bRow[i]) * N + col0 + bC4];
        }

#pragma unroll
        for (int k0 = 0; k0 < BK; k0 += 8) {
            uint32_t afrag[2][4];
            uint32_t bfrag[4][2];
#pragma unroll
            for (int mi = 0; mi < 2; mi++) {
                int r = wm * 32 + mi * 16 + g;
                afrag[mi][0] = As[r][k0 + q];
                afrag[mi][1] = As[r + 8][k0 + q];
                afrag[mi][2] = As[r][k0 + q + 4];
                afrag[mi][3] = As[r + 8][k0 + q + 4];
            }
#pragma unroll
            for (int ni = 0; ni < 4; ni++) {
                int n = wn * 32 + ni * 8 + g;
                bfrag[ni][0] = Bs[k0 + q][n];
                bfrag[ni][1] = Bs[k0 + q + 4][n];
            }
#pragma unroll
            for (int mi = 0; mi < 2; mi++)
#pragma unroll
                for (int ni = 0; ni < 4; ni++)
                    mma_tf32(acc[mi][ni], afrag[mi], bfrag[ni]);
        }
        __syncthreads();
    }

    // epilogue
#pragma unroll
    for (int mi = 0; mi < 2; mi++) {
#pragma unroll
        for (int ni = 0; ni < 4; ni++) {
            int r = row0 + wm * 32 + mi * 16 + g;
            int c = col0 + wn * 32 + ni * 8 + q * 2;
            *(float2*)&C[(size_t)r * N + c]       = make_float2(acc[mi][ni][0], acc[mi][ni][1]);
            *(float2*)&C[(size_t)(r + 8) * N + c] = make_float2(acc[mi][ni][2], acc[mi][ni][3]);
        }
    }
}

// ---------------- z_t kernel ----------------
// z[b,t,k] = sum_a tanh(cv[b,k,a] + cg[b,t,a]) * wh[a]
// grid (14 k-tiles, 32 b), 256 threads. cv row in registers (read once),
// cg cached in shared in two 16-row passes (32KB static smem).
__global__ __launch_bounds__(256) void zt_kernel(
    const float* __restrict__ cv, const float* __restrict__ cg,
    const float* __restrict__ wh, float* __restrict__ z)
{
    __shared__ float cg_sh[16 * Av];
    const int b = blockIdx.y;
    const int ktile = blockIdx.x;      // 0..13, 14 k's each
    const int tid = threadIdx.x;
    const int w = tid >> 5, lane = tid & 31;

    float whr[16];
#pragma unroll
    for (int i = 0; i < 16; i++) whr[i] = __ldg(wh + i * 32 + lane);

    for (int th = 0; th < 2; th++) {
        __syncthreads();
        const float4* src = (const float4*)(cg + ((size_t)b * Tv + th * 16) * Av);
        float4* dst = (float4*)cg_sh;
        for (int i = tid; i < 16 * Av / 4; i += 256) dst[i] = src[i];
        __syncthreads();

        for (int kl = w; kl < 14; kl += 8) {
            const int k = ktile * 14 + kl;
            const float* cvrow = cv + ((size_t)b * Kv + k) * Av + lane;
            float cvr[16];
#pragma unroll
            for (int i = 0; i < 16; i++) cvr[i] = cvrow[i * 32];

#pragma unroll 2
            for (int t = 0; t < 16; t++) {
                const float* cgrow = cg_sh + t * Av + lane;
                float s = 0.f;
#pragma unroll
                for (int i = 0; i < 16; i++)
                    s = fmaf(fast_tanh(cvr[i] + cgrow[i * 32]), whr[i], s);
                s = warp_sum(s);
                if (lane == 0)
                    z[((size_t)b * Tv + th * 16 + t) * Kv + k] = s;
            }
        }
    }
}

// ---------------- softmax + sentinel gate ----------------
__global__ __launch_bounds__(256) void softmax_kernel(
    const float* __restrict__ z, const float* __restrict__ csraw,
    const float* __restrict__ cg, const float* __restrict__ wh,
    float* __restrict__ alpha_out, float* __restrict__ beta_out)
{
    const int row = blockIdx.x;       // b*T + t
    const int tid = threadIdx.x;
    const int w = tid >> 5, lane = tid & 31;
    __shared__ float sred[8];
    __shared__ float sred2[8];

    // z_ext partial
    const float* cs_r = csraw + (size_t)row * Av;
    const float* cg_r = cg + (size_t)row * Av;
    float p = 0.f;
#pragma unroll
    for (int it = 0; it < 2; it++) {
        int a = tid + it * 256;
        p = fmaf(fast_tanh(cs_r[a] + cg_r[a]), __ldg(wh + a), p);
    }
    p = warp_sum(p);
    if (lane == 0) sred[w] = p;

    float v = (tid < Kv) ? z[(size_t)row * Kv + tid] : -1e30f;
    float m = warp_max(v);
    if (lane == 0) sred2[w] = m;
    __syncthreads();

    float zext = 0.f, m1 = -1e30f;
#pragma unroll
    for (int i = 0; i < 8; i++) { zext += sred[i]; m1 = fmaxf(m1, sred2[i]); }
    __syncthreads();

    float e = (tid < Kv) ? __expf(v - m1) : 0.f;
    float s = warp_sum(e);
    if (lane == 0) sred[w] = s;
    __syncthreads();

    float s1 = 0.f;
#pragma unroll
    for (int i = 0; i < 8; i++) s1 += sred[i];

    if (tid < Kv) alpha_out[(size_t)row * Kv + tid] = e / s1;

    if (tid == 0) {
        float m2 = fmaxf(m1, zext);
        float s2 = s1 * __expf(m1 - m2) + __expf(zext - m2);
        beta_out[row] = __expf(zext - m2) / s2;
    }
}

// ---------------- c_t + blend ----------------
__global__ __launch_bounds__(128) void ct_kernel(
    const float* __restrict__ att, const float* __restrict__ alpha,
    const float* __restrict__ beta, const float* __restrict__ sent,
    float* __restrict__ chat)
{
    __shared__ float al[Tv * Kv];
    __shared__ float be[Tv];
    const int b = blockIdx.y;
    const int h0 = blockIdx.x * 128;
    const int tid = threadIdx.x;

    for (int i = tid; i < Tv * Kv; i += 128) al[i] = alpha[(size_t)b * Tv * Kv + i];
    if (tid < Tv) be[tid] = beta[b * Tv + tid];
    __syncthreads();

    const int h = h0 + tid;
    float acc[Tv];
#pragma unroll
    for (int t = 0; t < Tv; t++) acc[t] = 0.f;

    const float* attb = att + (size_t)b * Kv * Hv + h;
#pragma unroll 2
    for (int k = 0; k < Kv; k++) {
        float a = attb[(size_t)k * Hv];
#pragma unroll
        for (int t = 0; t < Tv; t++) acc[t] = fmaf(al[t * Kv + k], a, acc[t]);
    }

#pragma unroll
    for (int t = 0; t < Tv; t++) {
        float bt = be[t];
        size_t idx = ((size_t)b * Tv + t) * Hv + h;
        chat[idx] = bt * sent[idx] + (1.f - bt) * acc[t];
    }
}

// ---------------- launch ----------------
extern "C" void kernel_launch(void* const* d_in, const int* in_sizes, int n_in,
                              void* d_out, int out_size)
{
    const float* att = (const float*)d_in[0];   // (B,K,H)
    const float* hid = (const float*)d_in[1];   // (B,T,H)
    const float* sen = (const float*)d_in[2];   // (B,T,H)
    const float* Wv  = (const float*)d_in[3];   // (H,A)
    const float* Wg  = (const float*)d_in[4];
    const float* Ws  = (const float*)d_in[5];
    const float* wh  = (const float*)d_in[6];   // (A,)

    float* out   = (float*)d_out;
    float* chat  = out;                                  // B*T*H
    float* alpha = out + (size_t)Bv * Tv * Hv;           // B*T*K
    float* beta  = alpha + (size_t)Bv * Tv * Kv;         // B*T

    float *cv, *cg, *cs, *zb;
    cudaGetSymbolAddress((void**)&cv, g_cv);
    cudaGetSymbolAddress((void**)&cg, g_cg);
    cudaGetSymbolAddress((void**)&cs, g_cs);
    cudaGetSymbolAddress((void**)&zb, g_z);

    dim3 gv(Av / 64, (Bv * Kv) / 128);   // 8 x 49
    gemm_tf32<<<gv, 256>>>(att, Wv, cv, Bv * Kv, Av, Hv);

    dim3 gg(Av / 64, (Bv * Tv) / 128);   // 8 x 8
    gemm_tf32<<<gg, 256>>>(hid, Wg, cg, Bv * Tv, Av, Hv);
    gemm_tf32<<<gg, 256>>>(sen, Ws, cs, Bv * Tv, Av, Hv);

    dim3 gz(14, Bv);
    zt_kernel<<<gz, 256>>>(cv, cg, wh, zb);

    softmax_kernel<<<Bv * Tv, 256>>>(zb, cs, cg, wh, alpha, beta);

    dim3 gc(Hv / 128, Bv);
    ct_kernel<<<gc, 128>>>(att, alpha, beta, sen, chat);
}